// round 16
// speedup vs baseline: 3.8177x; 1.0860x over previous
#include <cuda_runtime.h>
#include <cuda_bf16.h>
#include <cuda_fp16.h>
#include <math.h>
#include <stdint.h>

#define Bb  2
#define Ss  4096
#define DIMm 2048
#define Hh  16
#define HKk 8
#define HDd 128
#define Mm  128

#define INV_SQRT_M 0.08838834764831845f   // 128^{-0.5}
#define SCALE_QD   0.2973017787506803f    // 128^{-0.25}
#define EPSF 1e-6f

// ---------------- scratch (device globals; no allocations allowed) ----------
__device__ float g_v   [Bb*Ss*HKk*HDd];
__device__ float g_sqq [Bb*Hh*Ss];
__device__ float g_sqk [Bb*HKk*Ss];
__device__ float g_qphi[Bb*Hh*Ss*Mm];      // [b,h,s,m] fp32
__device__ float g_kxp [Bb*HKk*Ss*Mm];     // pre-exp key features fp32
__device__ unsigned g_kmaxe[Bb*HKk*Mm];    // encoded column max
__device__ float g_kvT [Bb*HKk*HDd*Mm];    // TRANSPOSED kv: [d][m]
__device__ float g_ksum[Bb*HKk*Mm];
__device__ float g_dn  [Bb*Hh*Ss];         // denominators

// pre-split operand arrays (packed x2 words)
#define XW (Bb*Ss*DIMm/2)
__device__ unsigned g_xfh [XW];            // x fp16 hi  (q,k,v GEMMs)
__device__ unsigned g_xfl [XW];            // x fp16 lo
__device__ unsigned g_wqh [Hh*HDd*DIMm/2];    // fp16 hi only
__device__ unsigned g_wkh [HKk*HDd*DIMm/2];
__device__ unsigned g_wvh [HKk*HDd*DIMm/2];
__device__ unsigned g_woh [DIMm*Hh*HDd/2];
__device__ unsigned g_aoh [Bb*Ss*Hh*HDd/2];   // attention out, fp16 hi
__device__ unsigned g_aol [Bb*Ss*Hh*HDd/2];   // attention out, fp16 lo
// bf16 hi/lo packed (favor operands)
__device__ unsigned g_qxh [Bb*Hh*Ss*HDd/2];
__device__ unsigned g_qxl [Bb*Hh*Ss*HDd/2];
__device__ unsigned g_kxh [Bb*HKk*Ss*HDd/2];
__device__ unsigned g_kxl [Bb*HKk*Ss*HDd/2];
__device__ unsigned g_pjh [Mm*HDd/2];
__device__ unsigned g_pjl [Mm*HDd/2];

// ---------------------------- helpers ---------------------------------------
__device__ __forceinline__ void bfsplit2(float x0, float x1, unsigned& hi, unsigned& lo) {
    __nv_bfloat162 h2 = __floats2bfloat162_rn(x0, x1);
    float2 hf = __bfloat1622float2(h2);
    __nv_bfloat162 l2 = __floats2bfloat162_rn(x0 - hf.x, x1 - hf.y);
    hi = *reinterpret_cast<unsigned*>(&h2);
    lo = *reinterpret_cast<unsigned*>(&l2);
}
__device__ __forceinline__ void hsplit2(float x0, float x1, unsigned& hi, unsigned& lo) {
    __half2 h2 = __floats2half2_rn(x0, x1);
    float2 hf = __half22float2(h2);
    __half2 l2 = __floats2half2_rn(x0 - hf.x, x1 - hf.y);
    hi = *reinterpret_cast<unsigned*>(&h2);
    lo = *reinterpret_cast<unsigned*>(&l2);
}
// order-preserving float<->unsigned encoding for atomicMax
__device__ __forceinline__ unsigned encf(float f) {
    int s = __float_as_int(f);
    return (s < 0) ? ~(unsigned)s : ((unsigned)s | 0x80000000u);
}
__device__ __forceinline__ float decf(unsigned u) {
    int s = (u & 0x80000000u) ? (int)(u & 0x7FFFFFFFu) : ~(int)u;
    return __int_as_float(s);
}

__device__ __forceinline__ void mma_bf16(float* d, const unsigned* a, const unsigned* b) {
    asm volatile(
        "mma.sync.aligned.m16n8k16.row.col.f32.bf16.bf16.f32 "
        "{%0,%1,%2,%3}, {%4,%5,%6,%7}, {%8,%9}, {%0,%1,%2,%3};\n"
        : "+f"(d[0]), "+f"(d[1]), "+f"(d[2]), "+f"(d[3])
        : "r"(a[0]), "r"(a[1]), "r"(a[2]), "r"(a[3]),
          "r"(b[0]), "r"(b[1]));
}
__device__ __forceinline__ void mma_f16(float* d, const unsigned* a, const unsigned* b) {
    asm volatile(
        "mma.sync.aligned.m16n8k16.row.col.f32.f16.f16.f32 "
        "{%0,%1,%2,%3}, {%4,%5,%6,%7}, {%8,%9}, {%0,%1,%2,%3};\n"
        : "+f"(d[0]), "+f"(d[1]), "+f"(d[2]), "+f"(d[3])
        : "r"(a[0]), "r"(a[1]), "r"(a[2]), "r"(a[3]),
          "r"(b[0]), "r"(b[1]));
}

#define CP16(dst, src) asm volatile("cp.async.cg.shared.global [%0], [%1], 16;\n" :: "r"(dst), "l"(src) : "memory")
#define CP_COMMIT()    asm volatile("cp.async.commit_group;\n" ::: "memory")
#define CP_WAIT0()     asm volatile("cp.async.wait_group 0;\n" ::: "memory")
#define LDMX4(r, addr) asm volatile( \
    "ldmatrix.sync.aligned.m8n8.x4.shared.b16 {%0,%1,%2,%3}, [%4];" \
    : "=r"((r)[0]), "=r"((r)[1]), "=r"((r)[2]), "=r"((r)[3]) : "r"(addr))

// ===== cp.async/ldmatrix smem layouts ========================================
#define P3 2560u
#define POFF_AH(st) ((unsigned)(st)*P3)
#define POFF_AL(st) (2u*P3 + (unsigned)(st)*P3)
#define POFF_BH(st) (4u*P3 + (unsigned)(st)*P3)
#define POFF_BL(st) (6u*P3 + (unsigned)(st)*P3)
#define DSMEM3_BYTES (6*2560*4)   // 61440 (3 arrays, fp16 2-term)
#define DSMEM4_BYTES (8*2560*4)   // 81920 (4 arrays, bf16 3-term)

// ---- 2-term fp16 (GEMMs) ----
#define CPA_LOAD(t0, st)                                                       \
    {                                                                          \
        int row = tid >> 1;                                                    \
        int ch  = (tid & 1) * 8;                                               \
        size_t g = (size_t)row * KW + ((size_t)(t0) << 4) + ch;                \
        unsigned d;                                                            \
        d = smb + (POFF_AH(st) + (unsigned)row*20u + ch)*4u;                   \
        CP16(d, Agh + g); CP16(d+16u, Agh + g + 4);                            \
        d = smb + (POFF_AL(st) + (unsigned)row*20u + ch)*4u;                   \
        CP16(d, Agl + g); CP16(d+16u, Agl + g + 4);                            \
        d = smb + (POFF_BH(st) + (unsigned)row*20u + ch)*4u;                   \
        CP16(d, Bgh + g); CP16(d+16u, Bgh + g + 4);                            \
        CP_COMMIT();                                                           \
    }

#define CPA_COMPUTE(st)                                                        \
    {                                                                          \
        _Pragma("unroll")                                                      \
        for (int h = 0; h < 2; h++) {                                          \
            int arow = (lane & 7) + ((lane >> 3) & 1) * 8;                     \
            int achw = 8*h + ((lane >> 4) & 1) * 4;                            \
            int brow = (lane & 7) + ((lane >> 4) & 1) * 8;                     \
            int bchw = 8*h + ((lane >> 3) & 1) * 4;                            \
            unsigned afh[4][4], afl[4][4], bf[2][4];                           \
            _Pragma("unroll")                                                  \
            for (int mi = 0; mi < 4; mi++) {                                   \
                unsigned ra = smb + (POFF_AH(st) +                             \
                    (unsigned)(warpM + mi*16 + arow)*20u + achw)*4u;           \
                LDMX4(afh[mi], ra);                                            \
                unsigned rl = smb + (POFF_AL(st) +                             \
                    (unsigned)(warpM + mi*16 + arow)*20u + achw)*4u;           \
                LDMX4(afl[mi], rl);                                            \
            }                                                                  \
            LDMX4(bf[0], smb + (POFF_BH(st) +                                  \
                (unsigned)(warpN + brow)*20u + bchw)*4u);                      \
            LDMX4(bf[1], smb + (POFF_BH(st) +                                  \
                (unsigned)(warpN + 16 + brow)*20u + bchw)*4u);                 \
            _Pragma("unroll")                                                  \
            for (int mi = 0; mi < 4; mi++) {                                   \
                mma_f16(acc[mi][0], afh[mi], &bf[0][0]);                       \
                mma_f16(acc[mi][0], afl[mi], &bf[0][0]);                       \
                mma_f16(acc[mi][1], afh[mi], &bf[0][2]);                       \
                mma_f16(acc[mi][1], afl[mi], &bf[0][2]);                       \
                mma_f16(acc[mi][2], afh[mi], &bf[1][0]);                       \
                mma_f16(acc[mi][2], afl[mi], &bf[1][0]);                       \
                mma_f16(acc[mi][3], afh[mi], &bf[1][2]);                       \
                mma_f16(acc[mi][3], afl[mi], &bf[1][2]);                       \
            }                                                                  \
        }                                                                      \
    }

#define CPA_MAINLOOP(KTILES)                                                   \
    CPA_LOAD(0, 0);                                                            \
    CP_WAIT0();                                                                \
    __syncthreads();                                                           \
    for (int t = 0; t < (KTILES); t++) {                                       \
        int st = t & 1;                                                        \
        bool has = (t + 1 < (KTILES));                                         \
        if (has) CPA_LOAD(t + 1, st ^ 1);                                      \
        CPA_COMPUTE(st);                                                       \
        if (has) CP_WAIT0();                                                   \
        __syncthreads();                                                       \
    }

// ---- 3-term bf16 (favor kernels), 4 arrays ----
#define CPA4_LOAD(t0, st)                                                      \
    {                                                                          \
        int row = tid >> 1;                                                    \
        int ch  = (tid & 1) * 8;                                               \
        size_t g = (size_t)row * KW + ((size_t)(t0) << 4) + ch;                \
        unsigned d;                                                            \
        d = smb + (POFF_AH(st) + (unsigned)row*20u + ch)*4u;                   \
        CP16(d, Agh + g); CP16(d+16u, Agh + g + 4);                            \
        d = smb + (POFF_AL(st) + (unsigned)row*20u + ch)*4u;                   \
        CP16(d, Agl + g); CP16(d+16u, Agl + g + 4);                            \
        d = smb + (POFF_BH(st) + (unsigned)row*20u + ch)*4u;                   \
        CP16(d, Bgh + g); CP16(d+16u, Bgh + g + 4);                            \
        d = smb + (POFF_BL(st) + (unsigned)row*20u + ch)*4u;                   \
        CP16(d, Bgl + g); CP16(d+16u, Bgl + g + 4);                            \
        CP_COMMIT();                                                           \
    }

#define CPA4_COMPUTE(st)                                                       \
    {                                                                          \
        _Pragma("unroll")                                                      \
        for (int h = 0; h < 2; h++) {                                          \
            int arow = (lane & 7) + ((lane >> 3) & 1) * 8;                     \
            int achw = 8*h + ((lane >> 4) & 1) * 4;                            \
            int brow = (lane & 7) + ((lane >> 4) & 1) * 8;                     \
            int bchw = 8*h + ((lane >> 3) & 1) * 4;                            \
            unsigned afh[4][4], afl[4][4], bfh[2][4], bfl[2][4];               \
            _Pragma("unroll")                                                  \
            for (int mi = 0; mi < 4; mi++) {                                   \
                LDMX4(afh[mi], smb + (POFF_AH(st) +                            \
                    (unsigned)(warpM + mi*16 + arow)*20u + achw)*4u);          \
                LDMX4(afl[mi], smb + (POFF_AL(st) +                            \
                    (unsigned)(warpM + mi*16 + arow)*20u + achw)*4u);          \
            }                                                                  \
            LDMX4(bfh[0], smb + (POFF_BH(st) +                                 \
                (unsigned)(warpN + brow)*20u + bchw)*4u);                      \
            LDMX4(bfh[1], smb + (POFF_BH(st) +                                 \
                (unsigned)(warpN + 16 + brow)*20u + bchw)*4u);                 \
            LDMX4(bfl[0], smb + (POFF_BL(st) +                                 \
                (unsigned)(warpN + brow)*20u + bchw)*4u);                      \
            LDMX4(bfl[1], smb + (POFF_BL(st) +                                 \
                (unsigned)(warpN + 16 + brow)*20u + bchw)*4u);                 \
            _Pragma("unroll")                                                  \
            for (int mi = 0; mi < 4; mi++) {                                   \
                mma_bf16(acc[mi][0], afh[mi], &bfh[0][0]);                     \
                mma_bf16(acc[mi][0], afl[mi], &bfh[0][0]);                     \
                mma_bf16(acc[mi][0], afh[mi], &bfl[0][0]);                     \
                mma_bf16(acc[mi][1], afh[mi], &bfh[0][2]);                     \
                mma_bf16(acc[mi][1], afl[mi], &bfh[0][2]);                     \
                mma_bf16(acc[mi][1], afh[mi], &bfl[0][2]);                     \
                mma_bf16(acc[mi][2], afh[mi], &bfh[1][0]);                     \
                mma_bf16(acc[mi][2], afl[mi], &bfh[1][0]);                     \
                mma_bf16(acc[mi][2], afh[mi], &bfl[1][0]);                     \
                mma_bf16(acc[mi][3], afh[mi], &bfh[1][2]);                     \
                mma_bf16(acc[mi][3], afl[mi], &bfh[1][2]);                     \
                mma_bf16(acc[mi][3], afh[mi], &bfl[1][2]);                     \
            }                                                                  \
        }                                                                      \
    }

#define CPA4_MAINLOOP(KTILES)                                                  \
    CPA4_LOAD(0, 0);                                                           \
    CP_WAIT0();                                                                \
    __syncthreads();                                                           \
    for (int t = 0; t < (KTILES); t++) {                                       \
        int st = t & 1;                                                        \
        bool has = (t + 1 < (KTILES));                                         \
        if (has) CPA4_LOAD(t + 1, st ^ 1);                                     \
        CPA4_COMPUTE(st);                                                      \
        if (has) CP_WAIT0();                                                   \
        __syncthreads();                                                       \
    }

#define CORE_PROLOG_VARS                                                       \
    int tid  = threadIdx.x;                                                    \
    int lane = tid & 31;                                                       \
    int warp = tid >> 5;                                                       \
    int warpM = (warp >> 2) * 64;                                              \
    int warpN = (warp & 3) * 32;                                               \
    float acc[4][4][4];                                                        \
    _Pragma("unroll")                                                          \
    for (int mi = 0; mi < 4; mi++)                                             \
        _Pragma("unroll")                                                      \
        for (int ni = 0; ni < 4; ni++)                                         \
            _Pragma("unroll")                                                  \
            for (int e = 0; e < 4; e++) acc[mi][ni][e] = 0.f;

// ---------------- fp32 -> packed hi/lo split kernels (MLP=2) ----------------
__global__ __launch_bounds__(256) void split_f16_kernel(
    const float* __restrict__ src, unsigned* __restrict__ hi,
    unsigned* __restrict__ lo, int nHalf)
{
    int i = blockIdx.x * blockDim.x + threadIdx.x;
    if (i >= nHalf) return;
    float4 v0 = ((const float4*)src)[i];
    float4 v1 = ((const float4*)src)[i + nHalf];
    unsigned h0, l0, h1, l1;
    hsplit2(v0.x, v0.y, h0, l0);
    hsplit2(v0.z, v0.w, h1, l1);
    ((uint2*)hi)[i] = make_uint2(h0, h1);
    ((uint2*)lo)[i] = make_uint2(l0, l1);
    hsplit2(v1.x, v1.y, h0, l0);
    hsplit2(v1.z, v1.w, h1, l1);
    ((uint2*)hi)[i + nHalf] = make_uint2(h0, h1);
    ((uint2*)lo)[i + nHalf] = make_uint2(l0, l1);
}
__global__ __launch_bounds__(256) void split_f16h_kernel(
    const float* __restrict__ src, unsigned* __restrict__ hi, int nHalf)
{
    int i = blockIdx.x * blockDim.x + threadIdx.x;
    if (i >= nHalf) return;
    float4 v0 = ((const float4*)src)[i];
    float4 v1 = ((const float4*)src)[i + nHalf];
    __half2 a0 = __floats2half2_rn(v0.x, v0.y);
    __half2 b0 = __floats2half2_rn(v0.z, v0.w);
    __half2 a1 = __floats2half2_rn(v1.x, v1.y);
    __half2 b1 = __floats2half2_rn(v1.z, v1.w);
    ((uint2*)hi)[i] = make_uint2(*reinterpret_cast<unsigned*>(&a0),
                                 *reinterpret_cast<unsigned*>(&b0));
    ((uint2*)hi)[i + nHalf] = make_uint2(*reinterpret_cast<unsigned*>(&a1),
                                         *reinterpret_cast<unsigned*>(&b1));
}
__global__ __launch_bounds__(256) void split_bf16_kernel(
    const float* __restrict__ src, unsigned* __restrict__ hi,
    unsigned* __restrict__ lo, int n4)
{
    int i = blockIdx.x * blockDim.x + threadIdx.x;
    if (i >= n4) return;
    float4 v = ((const float4*)src)[i];
    unsigned h0, l0, h1, l1;
    bfsplit2(v.x, v.y, h0, l0);
    bfsplit2(v.z, v.w, h1, l1);
    ((uint2*)hi)[i] = make_uint2(h0, h1);
    ((uint2*)lo)[i] = make_uint2(l0, l1);
}

// ------- 2-term fp16 GEMM + fused RMSNorm/RoPE epilogue (cp.async core) -----
__global__ __launch_bounds__(256, 2) void gemm_qk_fused(
    const unsigned* __restrict__ Ah, const unsigned* __restrict__ Al,
    const unsigned* __restrict__ Bh,
    const float* __restrict__ fc, const float* __restrict__ gvec,
    unsigned* __restrict__ xouth, unsigned* __restrict__ xoutl,
    float* __restrict__ sqout, int K, int nh)
{
    extern __shared__ unsigned sm[];
    __shared__ float red2[128][4][2];
    __shared__ float gsh[128];
    int rowBase = blockIdx.y * 128;
    int colBase = blockIdx.x * 128;
    const int KW = K >> 1;
    const unsigned* Agh = Ah + (size_t)rowBase * KW;
    const unsigned* Agl = Al + (size_t)rowBase * KW;
    const unsigned* Bgh = Bh + (size_t)colBase * KW;
    CORE_PROLOG_VARS;
    unsigned smb;
    asm("{ .reg .u64 t; cvta.to.shared.u64 t, %1; cvt.u32.u64 %0, t; }" : "=r"(smb) : "l"(sm));
    if (tid < 128) gsh[tid] = gvec[tid];
    int kTiles = K >> 5;
    CPA_MAINLOOP(kTiles);

    int mo = lane >> 2;
    #pragma unroll
    for (int mi = 0; mi < 4; mi++) {
        #pragma unroll
        for (int half = 0; half < 2; half++) {
            float s1 = 0.f, s2 = 0.f;
            #pragma unroll
            for (int ni = 0; ni < 4; ni++) {
                int c = warpN + ni*8 + (lane & 3)*2;
                float v0 = acc[mi][ni][2*half], v1 = acc[mi][ni][2*half+1];
                s1 += v0*v0 + v1*v1;
                float w0 = v0*gsh[c], w1 = v1*gsh[c+1];
                s2 += w0*w0 + w1*w1;
            }
            s1 += __shfl_xor_sync(0xffffffffu, s1, 1);
            s1 += __shfl_xor_sync(0xffffffffu, s1, 2);
            s2 += __shfl_xor_sync(0xffffffffu, s2, 1);
            s2 += __shfl_xor_sync(0xffffffffu, s2, 2);
            if ((lane & 3) == 0) {
                int rl = warpM + mi*16 + mo + half*8;
                red2[rl][warp & 3][0] = s1;
                red2[rl][warp & 3][1] = s2;
            }
        }
    }
    __syncthreads();
    #pragma unroll
    for (int mi = 0; mi < 4; mi++) {
        #pragma unroll
        for (int half = 0; half < 2; half++) {
            int rl = warpM + mi*16 + mo + half*8;
            float S1 = red2[rl][0][0]+red2[rl][1][0]+red2[rl][2][0]+red2[rl][3][0];
            float S2 = red2[rl][0][1]+red2[rl][1][1]+red2[rl][2][1]+red2[rl][3][1];
            float inv = rsqrtf(S1 * (1.0f/128.0f) + 1e-5f);
            int bs = rowBase + rl;
            int b = bs >> 12, s = bs & 4095;
            size_t rowoff = (((size_t)(b*nh + blockIdx.x))*Ss + s) * (HDd/2);
            #pragma unroll
            for (int ni = 0; ni < 4; ni++) {
                int c = warpN + ni*8 + (lane & 3)*2;
                float a  = acc[mi][ni][2*half]   * inv * gsh[c];
                float b2 = acc[mi][ni][2*half+1] * inv * gsh[c+1];
                float2 cs = ((const float2*)fc)[(size_t)bs * (HDd/2) + (c >> 1)];
                float r0 = (a*cs.x - b2*cs.y) * SCALE_QD;
                float r1 = (a*cs.y + b2*cs.x) * SCALE_QD;
                unsigned hi, lo;
                bfsplit2(r0, r1, hi, lo);
                xouth[rowoff + (c >> 1)] = hi;
                xoutl[rowoff + (c >> 1)] = lo;
            }
            if ((warp & 3) == 0 && (lane & 3) == 0)
                sqout[((size_t)(b*nh + blockIdx.x))*Ss + s] =
                    0.5f * SCALE_QD * SCALE_QD * inv * inv * S2;
        }
    }
}

// ------- 2-term fp16 GEMM, plain epilogue (cp.async core) -------------------
__global__ __launch_bounds__(256, 2) void gemm_f16_2t(
    const unsigned* __restrict__ Ah, const unsigned* __restrict__ Al,
    const unsigned* __restrict__ Bh,
    float* __restrict__ C, int K, int N)
{
    extern __shared__ unsigned sm[];
    int rowBase = blockIdx.y * 128;
    int colBase = blockIdx.x * 128;
    const int KW = K >> 1;
    const unsigned* Agh = Ah + (size_t)rowBase * KW;
    const unsigned* Agl = Al + (size_t)rowBase * KW;
    const unsigned* Bgh = Bh + (size_t)colBase * KW;
    CORE_PROLOG_VARS;
    unsigned smb;
    asm("{ .reg .u64 t; cvta.to.shared.u64 t, %1; cvt.u32.u64 %0, t; }" : "=r"(smb) : "l"(sm));
    int kTiles = K >> 5;
    CPA_MAINLOOP(kTiles);

    #pragma unroll
    for (int mi = 0; mi < 4; mi++) {
        int r = rowBase + warpM + mi * 16 + (lane >> 2);
        #pragma unroll
        for (int ni = 0; ni < 4; ni++) {
            int c = colBase + warpN + ni * 8 + (lane & 3) * 2;
            *(float2*)(C + (size_t)r * N + c) =
                make_float2(acc[mi][ni][0], acc[mi][ni][1]);
            *(float2*)(C + (size_t)(r + 8) * N + c) =
                make_float2(acc[mi][ni][2], acc[mi][ni][3]);
        }
    }
}

// ---- favor modes 0/1 with cp.async/ldmatrix 3-term bf16 core ---------------
__global__ __launch_bounds__(256, 2) void favor_cpa(
    const unsigned* __restrict__ Ah, const unsigned* __restrict__ Al,
    const unsigned* __restrict__ Bh, const unsigned* __restrict__ Bl,
    const float* __restrict__ sq, float* __restrict__ out,
    unsigned* __restrict__ kmaxe, int mode)
{
    extern __shared__ unsigned sm[];
    __shared__ float red[128][4];
    __shared__ unsigned smax[128];
    int rowBase = blockIdx.y * 128;
    const int KW = 64, N = 128;
    const unsigned* Agh = Ah + (size_t)rowBase * KW;
    const unsigned* Agl = Al + (size_t)rowBase * KW;
    const unsigned* Bgh = Bh;
    const unsigned* Bgl = Bl;
    CORE_PROLOG_VARS;
    unsigned smb;
    asm("{ .reg .u64 t; cvta.to.shared.u64 t, %1; cvt.u32.u64 %0, t; }" : "=r"(smb) : "l"(sm));
    if (mode == 1 && tid < 128) smax[tid] = 0u;
    CPA4_MAINLOOP(4);

    int mo = lane >> 2;
    if (mode == 0) {
        #pragma unroll
        for (int mi = 0; mi < 4; mi++) {
            float m0 = -1e30f, m1 = -1e30f;
            #pragma unroll
            for (int ni = 0; ni < 4; ni++) {
                m0 = fmaxf(m0, fmaxf(acc[mi][ni][0], acc[mi][ni][1]));
                m1 = fmaxf(m1, fmaxf(acc[mi][ni][2], acc[mi][ni][3]));
            }
            m0 = fmaxf(m0, __shfl_xor_sync(0xffffffffu, m0, 1));
            m0 = fmaxf(m0, __shfl_xor_sync(0xffffffffu, m0, 2));
            m1 = fmaxf(m1, __shfl_xor_sync(0xffffffffu, m1, 1));
            m1 = fmaxf(m1, __shfl_xor_sync(0xffffffffu, m1, 2));
            if ((lane & 3) == 0) {
                red[warpM + mi*16 + mo][warp & 3] = m0;
                red[warpM + mi*16 + mo + 8][warp & 3] = m1;
            }
        }
        __syncthreads();
        #pragma unroll
        for (int mi = 0; mi < 4; mi++) {
            int rl = warpM + mi*16 + mo;
            float rm0 = fmaxf(fmaxf(red[rl][0], red[rl][1]),
                              fmaxf(red[rl][2], red[rl][3]));
            float rm1 = fmaxf(fmaxf(red[rl+8][0], red[rl+8][1]),
                              fmaxf(red[rl+8][2], red[rl+8][3]));
            #pragma unroll
            for (int ni = 0; ni < 4; ni++) {
                int c = warpN + ni*8 + (lane & 3)*2;
                *(float2*)(out + (size_t)(rowBase + rl) * N + c) =
                    make_float2(__expf(acc[mi][ni][0]-rm0)*INV_SQRT_M + EPSF,
                                __expf(acc[mi][ni][1]-rm0)*INV_SQRT_M + EPSF);
                *(float2*)(out + (size_t)(rowBase + rl + 8) * N + c) =
                    make_float2(__expf(acc[mi][ni][2]-rm1)*INV_SQRT_M + EPSF,
                                __expf(acc[mi][ni][3]-rm1)*INV_SQRT_M + EPSF);
            }
        }
    } else {
        #pragma unroll
        for (int ni = 0; ni < 4; ni++) {
            float cm0 = -1e30f, cm1 = -1e30f;
            #pragma unroll
            for (int mi = 0; mi < 4; mi++) {
                int r0 = rowBase + warpM + mi*16 + mo;
                float s0 = sq[r0], s1 = sq[r0 + 8];
                int c = warpN + ni*8 + (lane & 3)*2;
                float o00 = acc[mi][ni][0]-s0, o01 = acc[mi][ni][1]-s0;
                float o10 = acc[mi][ni][2]-s1, o11 = acc[mi][ni][3]-s1;
                *(float2*)(out + (size_t)r0 * N + c)       = make_float2(o00, o01);
                *(float2*)(out + (size_t)(r0 + 8) * N + c) = make_float2(o10, o11);
                cm0 = fmaxf(cm0, fmaxf(o00, o10));
                cm1 = fmaxf(cm1, fmaxf(o01, o11));
            }
            cm0 = fmaxf(cm0, __shfl_xor_sync(0xffffffffu, cm0, 4));
            cm0 = fmaxf(cm0, __shfl_xor_sync(0xffffffffu, cm0, 8));
            cm0 = fmaxf(cm0, __shfl_xor_sync(0xffffffffu, cm0, 16));
            cm1 = fmaxf(cm1, __shfl_xor_sync(0xffffffffu, cm1, 4));
            cm1 = fmaxf(cm1, __shfl_xor_sync(0xffffffffu, cm1, 8));
            cm1 = fmaxf(cm1, __shfl_xor_sync(0xffffffffu, cm1, 16));
            if (mo == 0) {
                int c = warpN + ni*8 + (lane & 3)*2;
                atomicMax(&smax[c],   encf(cm0));
                atomicMax(&smax[c+1], encf(cm1));
            }
        }
        __syncthreads();
        if (tid < 128) {
            int bh = blockIdx.y >> 5;
            atomicMax(&kmaxe[bh * Mm + tid], smax[tid]);
        }
    }
}

// ---- mode-2 favor (old fp32-input core): out = qphi @ kvT + mask/denom -----
#define LDT 136
#define SOFF_AH2(b) ((unsigned)(b)*2176u)
#define SOFF_AL2(b) (4352u  + (unsigned)(b)*2176u)
#define SOFF_BH2(b) (8704u  + (unsigned)(b)*2176u)
#define SOFF_BL2(b) (13056u + (unsigned)(b)*2176u)
#define DSMEM_BYTES (17408*4)   // 69632

__global__ __launch_bounds__(256, 2) void favor_out(
    const float* __restrict__ A, const float* __restrict__ Bglob,
    const float* __restrict__ sq, const int* __restrict__ mask,
    unsigned* __restrict__ outh, unsigned* __restrict__ outl)
{
    extern __shared__ unsigned sm[];
    int rowBase = blockIdx.y * 128;
    const int K = 128;
    int bh0 = blockIdx.y >> 5;
    int b0 = bh0 >> 4, h0 = bh0 & 15;
    const float* Wg = Bglob + (size_t)(b0 * 8 + (h0 >> 1)) * 128 * 128;
    const float* Ag = A + (size_t)rowBase * K;
    CORE_PROLOG_VARS;
    int ldRow  = tid >> 1;
    int ldCol  = (tid & 1) * 16;
    int kpBase = (tid & 1) * 8;
    float ar[16], br[16];
    #define FO_LOAD(k0)                                                        \
        {                                                                      \
            const float* ap = Ag + (size_t)ldRow * K + (k0) + ldCol;           \
            const float* bp = Wg + (size_t)ldRow * K + (k0) + ldCol;           \
            float4 t;                                                          \
            t = *(const float4*)(ap);      ar[0]=t.x; ar[1]=t.y; ar[2]=t.z; ar[3]=t.w;   \
            t = *(const float4*)(ap + 4);  ar[4]=t.x; ar[5]=t.y; ar[6]=t.z; ar[7]=t.w;   \
            t = *(const float4*)(ap + 8);  ar[8]=t.x; ar[9]=t.y; ar[10]=t.z; ar[11]=t.w; \
            t = *(const float4*)(ap + 12); ar[12]=t.x; ar[13]=t.y; ar[14]=t.z; ar[15]=t.w;\
            t = *(const float4*)(bp);      br[0]=t.x; br[1]=t.y; br[2]=t.z; br[3]=t.w;   \
            t = *(const float4*)(bp + 4);  br[4]=t.x; br[5]=t.y; br[6]=t.z; br[7]=t.w;   \
            t = *(const float4*)(bp + 8);  br[8]=t.x; br[9]=t.y; br[10]=t.z; br[11]=t.w; \
            t = *(const float4*)(bp + 12); br[12]=t.x; br[13]=t.y; br[14]=t.z; br[15]=t.w;\
        }
    #define FO_STORE(bufn)                                                     \
        {                                                                      \
            _Pragma("unroll")                                                  \
            for (int e = 0; e < 8; e++) {                                      \
                unsigned hi, lo;                                               \
                bfsplit2(ar[2*e], ar[2*e+1], hi, lo);                          \
                sm[SOFF_AH2(bufn) + (kpBase+e)*LDT + ldRow] = hi;              \
                sm[SOFF_AL2(bufn) + (kpBase+e)*LDT + ldRow] = lo;              \
                bfsplit2(br[2*e], br[2*e+1], hi, lo);                          \
                sm[SOFF_BH2(bufn) + (kpBase+e)*LDT + ldRow] = hi;              \
                sm[SOFF_BL2(bufn) + (kpBase+e)*LDT + ldRow] = lo;              \
            }                                                                  \
        }
    FO_LOAD(0);
    FO_STORE(0);
    __syncthreads();
    for (int t = 0; t < 4; t++) {
        int buf = t & 1;
        bool has = (t + 1 < 4);
        if (has) FO_LOAD((t + 1) << 5);
        {
            #pragma unroll
            for (int h = 0; h < 2; h++) {
                int kc = h*8 + (lane & 3);
                int mo2 = lane >> 2;
                unsigned afh[4][4], afl[4][4], bfh[4][2], bfl[4][2];
                #pragma unroll
                for (int mi = 0; mi < 4; mi++) {
                    int m = warpM + mi * 16 + mo2;
                    afh[mi][0] = sm[SOFF_AH2(buf) + kc*LDT + m];
                    afh[mi][1] = sm[SOFF_AH2(buf) + kc*LDT + m + 8];
                    afh[mi][2] = sm[SOFF_AH2(buf) + (kc+4)*LDT + m];
                    afh[mi][3] = sm[SOFF_AH2(buf) + (kc+4)*LDT + m + 8];
                    afl[mi][0] = sm[SOFF_AL2(buf) + kc*LDT + m];
                    afl[mi][1] = sm[SOFF_AL2(buf) + kc*LDT + m + 8];
                    afl[mi][2] = sm[SOFF_AL2(buf) + (kc+4)*LDT + m];
                    afl[mi][3] = sm[SOFF_AL2(buf) + (kc+4)*LDT + m + 8];
                }
                #pragma unroll
                for (int ni = 0; ni < 4; ni++) {
                    int n = warpN + ni * 8 + mo2;
                    bfh[ni][0] = sm[SOFF_BH2(buf) + kc*LDT + n];
                    bfh[ni][1] = sm[SOFF_BH2(buf) + (kc+4)*LDT + n];
                    bfl[ni][0] = sm[SOFF_BL2(buf) + kc*LDT + n];
                    bfl[ni][1] = sm[SOFF_BL2(buf) + (kc+4)*LDT + n];
                }
                #pragma unroll
                for (int mi = 0; mi < 4; mi++)
                    #pragma unroll
                    for (int ni = 0; ni < 4; ni++) {
                        mma_bf16(acc[mi][ni], afh[mi], bfh[ni]);
                        mma_bf16(acc[mi][ni], afl[mi], bfh[ni]);
                        mma_bf16(acc[mi][ni], afh[mi], bfl[ni]);
                    }
            }
        }
        if (has) FO_STORE(buf ^ 1);
        __syncthreads();
    }

    int mo = lane >> 2;
    #pragma unroll
    for (int mi = 0; mi < 4; mi++) {
        int rg = rowBase + warpM + mi*16 + mo;
        #pragma unroll
        for (int half = 0; half < 2; half++) {
            int r = rg + half * 8;
            int s = r & 4095;
            int bh = r >> 12;
            int b = bh >> 4, h = bh & 15;
            float vm = (mask[b * Ss + s] > 0) ? 1.f : 0.f;
            float scale = vm / (sq[r] + EPSF);
            size_t base = ((size_t)(b * Ss + s) * (Hh*HDd)) + h * HDd;
            #pragma unroll
            for (int ni = 0; ni < 4; ni++) {
                int c = warpN + ni*8 + (lane & 3)*2;
                unsigned hi, lo;
                hsplit2(acc[mi][ni][2*half]*scale,
                        acc[mi][ni][2*half+1]*scale, hi, lo);
                size_t w = (base + c) >> 1;
                outh[w] = hi;
                outl[w] = lo;
            }
        }
    }
}

// ------------------- init: zero kvT/ksum, reset kmax encodings --------------
__global__ void init_kernel() {
    int i = blockIdx.x * blockDim.x + threadIdx.x;
    if (i < Bb*HKk*Mm*HDd) g_kvT[i] = 0.f;
    if (i < Bb*HKk*Mm) { g_ksum[i] = 0.f; g_kmaxe[i] = 0u; }
}

// -- kvT[d,m] += sum_s phi_k[s,m]*v[s,d] ; ksum[m] += sum_s phi_k[s,m] -------
__global__ __launch_bounds__(256) void kv_kernel(const int* __restrict__ mask)
{
    __shared__ float kps[16][128];
    __shared__ float vs [16][128];
    __shared__ float kmx[128];
    __shared__ float vmask[128];
    int bh = blockIdx.y;
    int b = bh / HKk, hk = bh % HKk;
    int s0 = blockIdx.x * 128;
    int tid = threadIdx.x;
    int tr = tid >> 4, tc = tid & 15;
    if (tid < 128) {
        kmx[tid] = decf(g_kmaxe[bh * Mm + tid]);
        vmask[tid] = (mask[b * Ss + s0 + tid] > 0) ? 1.f : 0.f;
    }
    __syncthreads();

    const float* KX = g_kxp + ((size_t)bh * Ss + s0) * Mm;
    const float* V  = g_v + ((size_t)(b * Ss + s0)) * (HKk*HDd) + hk * HDd;
    float acc[8][8];
    #pragma unroll
    for (int i=0;i<8;i++)
        #pragma unroll
        for (int j=0;j<8;j++) acc[i][j]=0.f;
    float ksacc = 0.f;

    for (int sc = 0; sc < 128; sc += 16) {
        #pragma unroll
        for (int it = 0; it < 2; it++) {
            int idx = tid + it * 256;
            int r = idx >> 5;
            int c4 = (idx & 31) << 2;
            float vm = vmask[sc + r];
            float4 x4 = *(const float4*)(KX + (size_t)(sc + r) * Mm + c4);
            kps[r][c4+0] = (__expf(x4.x - kmx[c4+0]) * INV_SQRT_M + EPSF) * vm;
            kps[r][c4+1] = (__expf(x4.y - kmx[c4+1]) * INV_SQRT_M + EPSF) * vm;
            kps[r][c4+2] = (__expf(x4.z - kmx[c4+2]) * INV_SQRT_M + EPSF) * vm;
            kps[r][c4+3] = (__expf(x4.w - kmx[c4+3]) * INV_SQRT_M + EPSF) * vm;
            float4 v4 = *(const float4*)(V + (size_t)(sc + r) * (HKk*HDd) + c4);
            vs[r][c4+0]=v4.x; vs[r][c4+1]=v4.y; vs[r][c4+2]=v4.z; vs[r][c4+3]=v4.w;
        }
        __syncthreads();
        #pragma unroll
        for (int ssi = 0; ssi < 16; ssi++) {
            float ra[8], rb[8];
            #pragma unroll
            for (int i=0;i<8;i++) ra[i]=kps[ssi][tr*8+i];
            #pragma unroll
            for (int j=0;j<8;j++) rb[j]=vs[ssi][tc*8+j];
            #pragma unroll
            for (int i=0;i<8;i++)
                #pragma unroll
                for (int j=0;j<8;j++) acc[i][j] += ra[i]*rb[j];
        }
        if (tid < 128) {
            #pragma unroll
            for (int ssi = 0; ssi < 16; ssi++) ksacc += kps[ssi][tid];
        }
        __syncthreads();
    }
    float* KV = g_kvT + (size_t)bh * Mm * HDd;
    #pragma unroll
    for (int i = 0; i < 8; i++)
        #pragma unroll
        for (int j = 0; j < 8; j++)
            atomicAdd(&KV[(size_t)(tc*8+j)*Mm + tr*8+i], acc[i][j]);
    if (tid < 128) atomicAdd(&g_ksum[bh * Mm + tid], ksacc);
}

// -------------- denominators: dn[row] = qphi[row,:]·ksum[bhk,:] -------------
__global__ __launch_bounds__(256) void dn_kernel() {
    int warp = threadIdx.x >> 5, lane = threadIdx.x & 31;
    int row = blockIdx.x * 8 + warp;
    int bh = row >> 12;
    int b = bh >> 4, h = bh & 15;
    int bhk = b * 8 + (h >> 1);
    float4 q = *(const float4*)(g_qphi + (size_t)row * Mm + lane * 4);
    float4 s = *(const float4*)(g_ksum + bhk * Mm + lane * 4);
    float v = q.x*s.x + q.y*s.y + q.z*s.z + q.w*s.w;
    #pragma unroll
    for (int o = 16; o > 0; o >>= 1) v += __shfl_xor_sync(0xffffffffu, v, o);
    if (lane == 0) g_dn[row] = v;
}

// ------------------------------- launch -------------------------------------
extern "C" void kernel_launch(void* const* d_in, const int* in_sizes, int n_in,
                              void* d_out, int out_size)
{
    const float* x    = (const float*)d_in[0];
    const int*   mask = (const int*)  d_in[1];
    const float* fc   = (const float*)d_in[2];
    const float* wq   = (const float*)d_in[3];
    const float* wk   = (const float*)d_in[4];
    const float* wv   = (const float*)d_in[5];
    const float* wo   = (const float*)d_in[6];
    const float* gq   = (const float*)d_in[7];
    const float* gk   = (const float*)d_in[8];
    const float* proj = (const float*)d_in[9];
    float* out = (float*)d_out;

    float *pv, *psqq, *psqk, *pqphi, *pkxp, *pkvT, *pdn;
    cudaGetSymbolAddress((void**)&pv,   g_v);
    cudaGetSymbolAddress((void**)&psqq, g_sqq);
    cudaGetSymbolAddress((void**)&psqk, g_sqk);
    cudaGetSymbolAddress((void**)&pqphi,g_qphi);
    cudaGetSymbolAddress((void**)&pkxp, g_kxp);
    cudaGetSymbolAddress((void**)&pkvT, g_kvT);
    cudaGetSymbolAddress((void**)&pdn,  g_dn);

    unsigned *xfh,*xfl,*wqh,*wkh,*wvh,*woh,*aoh,*aol;
    unsigned *qxh,*qxl,*kxh,*kxl,*pjh,*pjl,*kmaxe;
    cudaGetSymbolAddress((void**)&xfh, g_xfh); cudaGetSymbolAddress((void**)&xfl, g_xfl);
    cudaGetSymbolAddress((void**)&wqh, g_wqh);
    cudaGetSymbolAddress((void**)&wkh, g_wkh);
    cudaGetSymbolAddress((void**)&wvh, g_wvh);
    cudaGetSymbolAddress((void**)&woh, g_woh);
    cudaGetSymbolAddress((void**)&aoh, g_aoh); cudaGetSymbolAddress((void**)&aol, g_aol);
    cudaGetSymbolAddress((void**)&qxh, g_qxh); cudaGetSymbolAddress((void**)&qxl, g_qxl);
    cudaGetSymbolAddress((void**)&kxh, g_kxh); cudaGetSymbolAddress((void**)&kxl, g_kxl);
    cudaGetSymbolAddress((void**)&pjh, g_pjh); cudaGetSymbolAddress((void**)&pjl, g_pjl);
    cudaGetSymbolAddress((void**)&kmaxe, g_kmaxe);

    cudaFuncSetAttribute(gemm_qk_fused, cudaFuncAttributeMaxDynamicSharedMemorySize, DSMEM3_BYTES);
    cudaFuncSetAttribute(gemm_f16_2t,   cudaFuncAttributeMaxDynamicSharedMemorySize, DSMEM3_BYTES);
    cudaFuncSetAttribute(favor_cpa,     cudaFuncAttributeMaxDynamicSharedMemorySize, DSMEM4_BYTES);
    cudaFuncSetAttribute(favor_out,     cudaFuncAttributeMaxDynamicSharedMemorySize, DSMEM_BYTES);

    // side stream + events (host objects; created per call, not destroyed
    // while capture may reference them)
    cudaStream_t sA;
    cudaStreamCreateWithFlags(&sA, cudaStreamNonBlocking);
    cudaEvent_t evX, evW, evK, evKV;
    cudaEventCreateWithFlags(&evX,  cudaEventDisableTiming);
    cudaEventCreateWithFlags(&evW,  cudaEventDisableTiming);
    cudaEventCreateWithFlags(&evK,  cudaEventDisableTiming);
    cudaEventCreateWithFlags(&evKV, cudaEventDisableTiming);

    // --- s0: x split (MLP=2), fork point ------------------------------------
    split_f16_kernel <<<(Bb*Ss*DIMm/8 + 255)/256, 256>>>(x,  xfh, xfl, Bb*Ss*DIMm/8);
    cudaEventRecord(evX, 0);

    // --- sA: FIRST op is the event wait (forks sA into the capture) ----------
    cudaStreamWaitEvent(sA, evX, 0);
    split_f16h_kernel<<<(Hh*HDd*DIMm/8 + 255)/256, 256, 0, sA>>>(wq, wqh, Hh*HDd*DIMm/8);
    split_f16h_kernel<<<(HKk*HDd*DIMm/8 + 255)/256, 256, 0, sA>>>(wv, wvh, HKk*HDd*DIMm/8);
    split_f16h_kernel<<<(DIMm*Hh*HDd/8 + 255)/256, 256, 0, sA>>>(wo, woh, DIMm*Hh*HDd/8);
    split_bf16_kernel<<<(Mm*HDd/4 + 255)/256, 256, 0, sA>>>(proj, pjh, pjl, Mm*HDd/4);
    init_kernel<<<(Bb*HKk*Mm*HDd + 255)/256, 256, 0, sA>>>();
    cudaEventRecord(evW, sA);

    // --- s0: wk split + K projection -----------------------------------------
    split_f16h_kernel<<<(HKk*HDd*DIMm/8 + 255)/256, 256>>>(wk, wkh, HKk*HDd*DIMm/8);
    gemm_qk_fused<<<dim3(HKk, (Bb*Ss)/128), 256, DSMEM3_BYTES>>>(
        xfh, xfl, wkh, fc, gk, kxh, kxl, psqk, DIMm, HKk);
    cudaEventRecord(evK, 0);

    // --- sA: V projection -> favorK -> kv (in qGEMM's shadow) ----------------
    gemm_f16_2t<<<dim3((HKk*HDd)/128, (Bb*Ss)/128), 256, DSMEM3_BYTES, sA>>>(
        xfh, xfl, wvh, pv, DIMm, HKk*HDd);
    cudaStreamWaitEvent(sA, evK, 0);
    favor_cpa<<<dim3(1, (Bb*HKk*Ss)/128), 256, DSMEM4_BYTES, sA>>>(
        kxh, kxl, pjh, pjl, psqk, pkxp, kmaxe, 1);
    kv_kernel<<<dim3(Ss/128, Bb*HKk), 256, 0, sA>>>(mask);
    cudaEventRecord(evKV, sA);

    // --- s0: Q projection + favorQ (needs wqh/pj from sA) --------------------
    cudaStreamWaitEvent(0, evW, 0);
    gemm_qk_fused<<<dim3(Hh, (Bb*Ss)/128), 256, DSMEM3_BYTES>>>(
        xfh, xfl, wqh, fc, gq, qxh, qxl, psqq, DIMm, Hh);
    favor_cpa<<<dim3(1, (Bb*Hh*Ss)/128), 256, DSMEM4_BYTES>>>(
        qxh, qxl, pjh, pjl, psqq, pqphi, kmaxe, 0);

    // --- s0: join kv, then denominators + attention out + output projection --
    cudaStreamWaitEvent(0, evKV, 0);
    dn_kernel<<<(Bb*Hh*Ss)/8, 256>>>();
    favor_out<<<dim3(1, (Bb*Hh*Ss)/128), 256, DSMEM_BYTES>>>(
        pqphi, pkvT, pdn, mask, aoh, aol);
    gemm_f16_2t<<<dim3(DIMm/128, (Bb*Ss)/128), 256, DSMEM3_BYTES>>>(
        aoh, aol, woh, out, Hh*HDd, DIMm);
}